// round 15
// baseline (speedup 1.0000x reference)
#include <cuda_runtime.h>
#include <cuda_bf16.h>
#include <cstdint>

#define GNX 512
#define GNY 512
#define GP (GNX * GNY)            // 262144 pillars
#define GB 4
#define GNPTS 100000
#define GC 64
#define TILE_P 64                 // pillars per tile (one gather block)
#define TILES_PER_B (GP / TILE_P) // 4096
#define NTILES (GB * TILES_PER_B) // 16384
#define NCELLS (GB * GP)          // 1048576 (b, pillar) cells
#define CAP_P 8                   // bucket capacity per cell (lambda = 0.38)
#define NPTS_TOTAL (GB * GNPTS)   // 400000
#define OVF_MAX 4096

// Per-cell buckets: 1M cells * 8 entries * 4B = 32 MB list + 4 MB cursors.
// Cursors zeroed at module load, re-zeroed by gather each call (same thread
// reads then zeroes -> no cross-warp race). Overflow counter by spill.
__device__ int      g_cursor[NCELLS];
__device__ unsigned g_list[(size_t)NCELLS * CAP_P];
__device__ int      g_ovf_cnt;
__device__ uint2    g_ovf[OVF_MAX];

// ---------------------------------------------------------------------------
// K1: fill per-cell buckets. 4 points/thread via int4 (4 independent ATOMG
// chains). Entry = bare global point id (pillar implicit in the cell).
// Indices are int32 on the wire (JAX x64-off). GNPTS % 4 == 0.
// ---------------------------------------------------------------------------
__global__ void fill_kernel(const int* __restrict__ indices) {
    int t = blockIdx.x * blockDim.x + threadIdx.x;
    if (t >= NPTS_TOTAL / 4) return;
    int b = (t * 4) / GNPTS;
    int4 p4 = reinterpret_cast<const int4*>(indices)[t];
    int p[4] = {p4.x, p4.y, p4.z, p4.w};
#pragma unroll
    for (int k = 0; k < 4; k++) {
        if (p[k] >= 0 && p[k] < GP) {
            int cell = b * GP + p[k];
            int pos = atomicAdd(&g_cursor[cell], 1);
            unsigned gid = (unsigned)(t * 4 + k);
            if (pos < CAP_P) {
                g_list[(size_t)cell * CAP_P + pos] = gid;
            } else {
                int o = atomicAdd(&g_ovf_cnt, 1);
                if (o < OVF_MAX) g_ovf[o] = make_uint2(gid, (unsigned)p[k]);
            }
        }
    }
}

// ---------------------------------------------------------------------------
// K2: gather, ATOMIC-FREE. One block per 64-pillar tile; each half-warp
// exclusively owns 4 pillars, accumulating all 64 channels of them in
// registers (lane lh holds channels 4lh..4lh+3 of each owned pillar).
// Per entry: 16 lanes read the 256B feature row as float4 (__ldcs, full
// sectors) and FADD into registers — no smem atomics anywhere.
// Register dump to smem (plain STS, once per tile) replaces the zero-init,
// then the same coalesced __stwt 16KB output store.
// R13/R14 established the ATOMS pipe as the binding constraint at ~0.9
// cyc/lane regardless of banking or pipelining — this removes it entirely.
// ---------------------------------------------------------------------------
__global__ void __launch_bounds__(256) gather_kernel(const float* __restrict__ x,
                                                     float* __restrict__ out) {
    __shared__ float acc[GC][TILE_P + 1];
    __shared__ int   cnt_s[TILE_P];

    int tid  = threadIdx.x;
    int tile = blockIdx.x;
    int b    = tile / TILES_PER_B;
    int p0   = (tile % TILES_PER_B) << 6;
    int cell0 = b * GP + p0;

    if (tid < TILE_P) {                       // coalesced 256B cursor read
        int c = g_cursor[cell0 + tid];
        g_cursor[cell0 + tid] = 0;            // same-thread zero: race-free
        cnt_s[tid] = min(c, CAP_P);
    }
    __syncthreads();

    int wid  = tid >> 5;
    int lane = tid & 31;
    int half = lane >> 4;
    int lh   = lane & 15;
    int g    = wid * 2 + half;                // half-warp group 0..15

    float a[16];
#pragma unroll
    for (int i = 0; i < 16; i++) a[i] = 0.0f;

#pragma unroll
    for (int j = 0; j < 4; j++) {
        int ploc = g * 4 + j;
        int cnt  = cnt_s[ploc];
        const unsigned* lst = g_list + (size_t)(cell0 + ploc) * CAP_P;
        for (int i = 0; i < cnt; i++) {
            unsigned gid = lst[i];            // uniform in half-warp: broadcast
            float4 v = __ldcs(reinterpret_cast<const float4*>(
                                  x + (size_t)gid * GC) + lh);
            a[4 * j + 0] += v.x;
            a[4 * j + 1] += v.y;
            a[4 * j + 2] += v.z;
            a[4 * j + 3] += v.w;
        }
    }

    // dump registers: channels 4lh..4lh+3 of the 4 owned pillars
#pragma unroll
    for (int j = 0; j < 4; j++) {
        int ploc = g * 4 + j;
        acc[4 * lh + 0][ploc] = a[4 * j + 0];
        acc[4 * lh + 1][ploc] = a[4 * j + 1];
        acc[4 * lh + 2][ploc] = a[4 * j + 2];
        acc[4 * lh + 3][ploc] = a[4 * j + 3];
    }
    __syncthreads();

    float* obase = out + ((size_t)b * GC) * GP + p0;
    for (int i = tid; i < GC * (TILE_P / 4); i += 256) {
        int c = i >> 4;
        int q = (i & 15) << 2;
        float4 v4 = make_float4(acc[c][q], acc[c][q + 1],
                                acc[c][q + 2], acc[c][q + 3]);
        __stwt(reinterpret_cast<float4*>(obase + (size_t)c * GP + q), v4);
    }
}

// ---------------------------------------------------------------------------
// K3: spill — bucket overflow (normally zero entries). Single block, runs
// after gather so atomicAdd into the already-written out is correct.
// Re-zeroes the overflow counter for the next invocation.
// ---------------------------------------------------------------------------
__global__ void spill_kernel(const float* __restrict__ x,
                             float* __restrict__ out) {
    int cnt = g_ovf_cnt;
    if (cnt > OVF_MAX) cnt = OVF_MAX;
    int tid = threadIdx.x;
    for (int w = tid; w < cnt * 16; w += 256) {
        int e  = w >> 4;
        int c4 = (w & 15) << 2;
        uint2 ent = g_ovf[e];
        unsigned gid = ent.x;
        int p = (int)ent.y;
        int b = gid / GNPTS;
        float4 v = *reinterpret_cast<const float4*>(x + (size_t)gid * GC + c4);
        float* o = out + ((size_t)b * GC + c4) * GP + p;
        atomicAdd(o + 0 * (size_t)GP, v.x);
        atomicAdd(o + 1 * (size_t)GP, v.y);
        atomicAdd(o + 2 * (size_t)GP, v.z);
        atomicAdd(o + 3 * (size_t)GP, v.w);
    }
    __syncthreads();
    if (tid == 0) g_ovf_cnt = 0;
}

extern "C" void kernel_launch(void* const* d_in, const int* in_sizes, int n_in,
                              void* d_out, int out_size) {
    const float* x   = (const float*)d_in[0];   // (B, N, C) fp32
    const int*   idx = (const int*)d_in[1];     // (B, N) int32
    float*       out = (float*)d_out;           // (B, C, NX, NY) fp32

    (void)in_sizes; (void)n_in; (void)out_size;

    fill_kernel<<<(NPTS_TOTAL / 4 + 255) / 256, 256>>>(idx);
    gather_kernel<<<NTILES, 256>>>(x, out);
    spill_kernel<<<1, 256>>>(x, out);
}